// round 1
// baseline (speedup 1.0000x reference)
#include <cuda_runtime.h>

#define DIM 128
#define SA 132   // smem stride for activation tile (k-major), floats
#define SW 132   // smem stride for weight tiles (k-major), floats
#define THREADS 256
#define PI_F 3.14159265358979323846f

// ---------- packed f32x2 helpers (sm_103a FFMA2 path) ----------
__device__ __forceinline__ unsigned long long pack_dup(float a) {
    unsigned long long r;
    asm("mov.b64 %0, {%1, %1};" : "=l"(r) : "f"(a));
    return r;
}
__device__ __forceinline__ void ffma2(unsigned long long& acc,
                                      unsigned long long a,
                                      unsigned long long b) {
    asm("fma.rn.f32x2 %0, %1, %2, %0;" : "+l"(acc) : "l"(a), "l"(b));
}
__device__ __forceinline__ float2 unpack2(unsigned long long v) {
    float2 f;
    asm("mov.b64 {%0, %1}, %2;" : "=f"(f.x), "=f"(f.y) : "l"(v));
    return f;
}
__device__ __forceinline__ float silu_f(float z) {
    // z * sigmoid(z); __expf error ~2^-21, far under 1e-3 budget.
    return z / (1.0f + __expf(-z));
}

// 128-deep K loop: acc[i][p] accumulates C[row=ty*8+i][colpair p]
// col pairs: p0=(c0,c0+1), p1=(c0+2,c0+3), p2=(64+c0,64+c0+1), p3=(64+c0+2,64+c0+3), c0=tx*4
__device__ __forceinline__ void gemm128(const float* __restrict__ sAct,
                                        const float* __restrict__ sWt,
                                        int tx, int ty,
                                        unsigned long long acc[8][4]) {
#pragma unroll
    for (int i = 0; i < 8; ++i)
#pragma unroll
        for (int p = 0; p < 4; ++p) acc[i][p] = 0ULL;

#pragma unroll 4
    for (int k = 0; k < DIM; ++k) {
        // A: k-major [k][row]; 8 rows for this thread, broadcast-friendly
        const float4 a03 = *(const float4*)(sAct + k * SA + ty * 8);
        const float4 a47 = *(const float4*)(sAct + k * SA + ty * 8 + 4);
        // W: k-major [k][o]; two contiguous 4-col chunks
        const ulonglong2 w0 = *(const ulonglong2*)(sWt + k * SW + tx * 4);
        const ulonglong2 w1 = *(const ulonglong2*)(sWt + k * SW + 64 + tx * 4);

        unsigned long long aa[8];
        aa[0] = pack_dup(a03.x); aa[1] = pack_dup(a03.y);
        aa[2] = pack_dup(a03.z); aa[3] = pack_dup(a03.w);
        aa[4] = pack_dup(a47.x); aa[5] = pack_dup(a47.y);
        aa[6] = pack_dup(a47.z); aa[7] = pack_dup(a47.w);

#pragma unroll
        for (int i = 0; i < 8; ++i) {
            ffma2(acc[i][0], aa[i], w0.x);
            ffma2(acc[i][1], aa[i], w0.y);
            ffma2(acc[i][2], aa[i], w1.x);
            ffma2(acc[i][3], aa[i], w1.y);
        }
    }
}

__global__ void __launch_bounds__(THREADS, 1)
fused_timestep_mlp(const float* __restrict__ t,
                   const float* __restrict__ W1,
                   const float* __restrict__ b1,
                   const float* __restrict__ W2,
                   const float* __restrict__ b2,
                   float* __restrict__ out) {
    extern __shared__ float sm[];
    float* sW1 = sm;                  // [128][SW] k-major: sW1[k*SW+o] = W1[o][k]
    float* sW2 = sm + DIM * SW;       // [128][SW] k-major
    float* sA  = sm + 2 * DIM * SW;   // [128][SA] k-major activations

    const int tid = threadIdx.x;
    const int tx = tid & 15;          // 16 col groups
    const int ty = tid >> 4;          // 16 row groups (8 rows each)
    const int rowBase = blockIdx.x * DIM;

    // ---- Phase 1: load W1/W2 transposed into smem (conflict-free STS) ----
    {
        const int o   = tid & 127;        // output index (smem col) = lane-distinct
        const int kq0 = tid >> 7;         // 0/1
#pragma unroll
        for (int it = 0; it < 16; ++it) {
            const int kq = kq0 + it * 2;  // 0..31 k-quads
            const float4 v1 = *(const float4*)(W1 + o * DIM + kq * 4);
            const float4 v2 = *(const float4*)(W2 + o * DIM + kq * 4);
            sW1[(kq * 4 + 0) * SW + o] = v1.x;
            sW1[(kq * 4 + 1) * SW + o] = v1.y;
            sW1[(kq * 4 + 2) * SW + o] = v1.z;
            sW1[(kq * 4 + 3) * SW + o] = v1.w;
            sW2[(kq * 4 + 0) * SW + o] = v2.x;
            sW2[(kq * 4 + 1) * SW + o] = v2.y;
            sW2[(kq * 4 + 2) * SW + o] = v2.z;
            sW2[(kq * 4 + 3) * SW + o] = v2.w;
        }
    }

    // ---- Phase 2: timestep embedding, stored k-major sA[d][row] ----
    {
        const int row = tid >> 1;
        const int d0  = (tid & 1) * 64;
        const float tv = t[rowBase + row];
        const float p1 = tv * (PI_F / 128.0f);
        const float p2 = (1.0f - tv) * (PI_F / 128.0f);
#pragma unroll 8
        for (int j = 0; j < 64; ++j) {
            const int d = d0 + j;
            const float df = (float)d;
            const float e = tv * __cosf(df * p1) + tv * __sinf(df * p2);
            sA[d * SA + row] = e;
        }
    }
    __syncthreads();

    unsigned long long acc[8][4];
    float rb[8];

    // ---- Layer 1 ----
    gemm128(sA, sW1, tx, ty, acc);
#pragma unroll
    for (int j = 0; j < 4; ++j) {
        rb[j]     = b1[tx * 4 + j];
        rb[4 + j] = b1[64 + tx * 4 + j];
    }
    float h[8][8];  // [row i][col j: 0..3 -> c0+j, 4..7 -> 64+c0+(j-4)]
#pragma unroll
    for (int i = 0; i < 8; ++i) {
#pragma unroll
        for (int p = 0; p < 4; ++p) {
            const float2 z = unpack2(acc[i][p]);
            const int j = 2 * p;
            h[i][j]     = silu_f(z.x + rb[j]);
            h[i][j + 1] = silu_f(z.y + rb[j + 1]);
        }
    }
    __syncthreads();  // all GEMM1 reads of sA done before overwrite

    // store h back into sA, k-major: sA[c][row] = h[row][c]
#pragma unroll
    for (int jc = 0; jc < 8; ++jc) {
        const int col = (jc < 4) ? (tx * 4 + jc) : (64 + tx * 4 + (jc - 4));
        const float4 v0 = make_float4(h[0][jc], h[1][jc], h[2][jc], h[3][jc]);
        const float4 v1 = make_float4(h[4][jc], h[5][jc], h[6][jc], h[7][jc]);
        *(float4*)(sA + col * SA + ty * 8)     = v0;
        *(float4*)(sA + col * SA + ty * 8 + 4) = v1;
    }
    __syncthreads();

    // ---- Layer 2 ----
    gemm128(sA, sW2, tx, ty, acc);
#pragma unroll
    for (int j = 0; j < 4; ++j) {
        rb[j]     = b2[tx * 4 + j];
        rb[4 + j] = b2[64 + tx * 4 + j];
    }
#pragma unroll
    for (int i = 0; i < 8; ++i) {
        const int row = rowBase + ty * 8 + i;
        const float2 z0 = unpack2(acc[i][0]);
        const float2 z1 = unpack2(acc[i][1]);
        const float2 z2 = unpack2(acc[i][2]);
        const float2 z3 = unpack2(acc[i][3]);
        const float4 va = make_float4(silu_f(z0.x + rb[0]), silu_f(z0.y + rb[1]),
                                      silu_f(z1.x + rb[2]), silu_f(z1.y + rb[3]));
        const float4 vb = make_float4(silu_f(z2.x + rb[4]), silu_f(z2.y + rb[5]),
                                      silu_f(z3.x + rb[6]), silu_f(z3.y + rb[7]));
        *(float4*)(out + (size_t)row * DIM + tx * 4)      = va;
        *(float4*)(out + (size_t)row * DIM + 64 + tx * 4) = vb;
    }
}

extern "C" void kernel_launch(void* const* d_in, const int* in_sizes, int n_in,
                              void* d_out, int out_size) {
    const float* t  = (const float*)d_in[0];
    const float* W1 = (const float*)d_in[1];
    const float* b1 = (const float*)d_in[2];
    const float* W2 = (const float*)d_in[3];
    const float* b2 = (const float*)d_in[4];
    float* out = (float*)d_out;

    const int B = in_sizes[0];
    const int smem_bytes = (2 * DIM * SW + DIM * SA) * (int)sizeof(float);  // ~198 KB

    // idempotent, safe during graph capture (not a stream op)
    cudaFuncSetAttribute(fused_timestep_mlp,
                         cudaFuncAttributeMaxDynamicSharedMemorySize, smem_bytes);

    fused_timestep_mlp<<<B / DIM, THREADS, smem_bytes>>>(t, W1, b1, W2, b2, out);
}